// round 14
// baseline (speedup 1.0000x reference)
#include <cuda_runtime.h>
#include <cuda_fp16.h>
#include <cstdint>
#include <math.h>

#define B_  2
#define H_  2048
#define L_  4096
#define LK  128
#define LAM 0.003f

// Scratch: gelu(conv(u)+D*u) as fp16, layout [B, H, L]
__device__ __half g_y[(size_t)B_ * H_ * L_];
// fp16 copy of W [2H, H]
__device__ __half g_wh[(size_t)2 * H_ * H_];

// ============================================================================
// Helpers
// ============================================================================
__device__ __forceinline__ uint32_t smem_to_u32(const void* p) {
    uint32_t a;
    asm("{ .reg .u64 t; cvta.to.shared.u64 t, %1; cvt.u32.u64 %0, t; }"
        : "=r"(a) : "l"(p));
    return a;
}
__device__ __forceinline__ void cp16(uint32_t dst, const void* src) {
    asm volatile("cp.async.cg.shared.global [%0], [%1], 16;"
                 :: "r"(dst), "l"(src));
}
#define CP_COMMIT() asm volatile("cp.async.commit_group;" ::: "memory")
#define CP_WAIT(N)  asm volatile("cp.async.wait_group %0;" :: "n"(N) : "memory")

#define LDMATRIX_X2(r0, r1, addr) \
    asm volatile("ldmatrix.sync.aligned.m8n8.x2.shared.b16 {%0,%1}, [%2];" \
                 : "=r"(r0), "=r"(r1) : "r"(addr))

#define LDMATRIX_X4(r0, r1, r2, r3, addr) \
    asm volatile("ldmatrix.sync.aligned.m8n8.x4.shared.b16 {%0,%1,%2,%3}, [%4];" \
                 : "=r"(r0), "=r"(r1), "=r"(r2), "=r"(r3) : "r"(addr))

#define LDMATRIX_X4_TRANS(r0, r1, r2, r3, addr) \
    asm volatile("ldmatrix.sync.aligned.m8n8.x4.trans.shared.b16 {%0,%1,%2,%3}, [%4];" \
                 : "=r"(r0), "=r"(r1), "=r"(r2), "=r"(r3) : "r"(addr))

// fp32-accum mma (conv kernel)
__device__ __forceinline__ void mma_f16(float* c, const uint32_t* a, const uint32_t* b) {
    asm volatile(
        "mma.sync.aligned.m16n8k16.row.col.f32.f16.f16.f32 "
        "{%0,%1,%2,%3}, {%4,%5,%6,%7}, {%8,%9}, {%0,%1,%2,%3};"
        : "+f"(c[0]), "+f"(c[1]), "+f"(c[2]), "+f"(c[3])
        : "r"(a[0]), "r"(a[1]), "r"(a[2]), "r"(a[3]), "r"(b[0]), "r"(b[1]));
}

// fp16-accum mma, C = 0, single rounding of the k=16 dot; promoted in fp32
__device__ __forceinline__ void mma_f16h_acc(float* acc, const uint32_t* a,
                                             const uint32_t* b) {
    uint32_t d0, d1;
    const uint32_t z = 0u;
    asm volatile(
        "mma.sync.aligned.m16n8k16.row.col.f16.f16.f16.f16 "
        "{%0,%1}, {%2,%3,%4,%5}, {%6,%7}, {%8,%9};"
        : "=r"(d0), "=r"(d1)
        : "r"(a[0]), "r"(a[1]), "r"(a[2]), "r"(a[3]),
          "r"(b[0]), "r"(b[1]), "r"(z), "r"(z));
    float2 lo = __half22float2(*(__half2*)&d0);
    float2 hi = __half22float2(*(__half2*)&d1);
    acc[0] += lo.x; acc[1] += lo.y;
    acc[2] += hi.x; acc[3] += hi.y;
}

// ============================================================================
// Kernel 1: fused. Blocks [0,4096): Toeplitz tensor-core FIR conv + fp32 D
// skip + exact GELU -> fp16. Blocks [4096,6144): W -> fp16 conversion.
// ============================================================================
#define NCONV (B_ * H_)
#define NWCVT 2048

__global__ __launch_bounds__(128) void conv_gelu_mma(
    const float* __restrict__ u,
    const float* __restrict__ kern,
    const float* __restrict__ D,
    const float* __restrict__ W)
{
    const int tid = threadIdx.x;

    if (blockIdx.x >= NCONV) {
        size_t base = ((size_t)(blockIdx.x - NCONV) * 4096) + (size_t)tid * 8;
        #pragma unroll
        for (int it = 0; it < 4; it++) {
            size_t i = base + (size_t)it * 1024;
            float4 v0 = *(const float4*)(W + i);
            float4 v1 = *(const float4*)(W + i + 4);
            __half2 hh[4];
            hh[0] = __floats2half2_rn(v0.x, v0.y);
            hh[1] = __floats2half2_rn(v0.z, v0.w);
            hh[2] = __floats2half2_rn(v1.x, v1.y);
            hh[3] = __floats2half2_rn(v1.z, v1.w);
            *(uint4*)(g_wh + i) = *(const uint4*)hh;
        }
        return;
    }

    __shared__ __half uh[4224];
    __shared__ __half At[9][16][24];
    __shared__ float  ks[LK];
    __shared__ float  buf[4][16][10];

    const int bh   = blockIdx.x;
    const int b    = bh / H_;
    const int h    = bh % H_;
    const int wid  = tid >> 5;
    const int lane = tid & 31;

    const float* urow = u   + ((size_t)b * H_ + h) * L_;
    __half*      yrow = g_y + ((size_t)b * H_ + h) * L_;

    {
        float kv = kern[h * LK + tid];
        float a  = fabsf(kv) - LAM;
        a = a > 0.f ? a : 0.f;
        ks[tid] = (kv > 0.f) ? a : ((kv < 0.f) ? -a : 0.f);
    }
    for (int idx = tid; idx < 4224; idx += 128) {
        int l = idx - 128;
        uh[idx] = (l >= 0) ? __float2half_rn(urow[l]) : __float2half_rn(0.f);
    }
    __syncthreads();
    for (int e = tid; e < 9 * 256; e += 128) {
        int s = e >> 8, rr = e & 255, i = rr >> 4, t = rr & 15;
        int d = i - t + 16 * s;
        At[s][i][t] = (d >= 0 && d < LK) ? __float2half_rn(ks[d])
                                         : __float2half_rn(0.f);
    }
    __syncthreads();

    const int r = lane >> 2;
    const int c = lane & 3;
    uint32_t af[9][4];
    #pragma unroll
    for (int s = 0; s < 9; s++) {
        af[s][0] = *(const uint32_t*)&At[s][r][2 * c];
        af[s][1] = *(const uint32_t*)&At[s][r + 8][2 * c];
        af[s][2] = *(const uint32_t*)&At[s][r][2 * c + 8];
        af[s][3] = *(const uint32_t*)&At[s][r + 8][2 * c + 8];
    }

    const uint32_t uh_u32 = smem_to_u32(uh);
    const int lm = (lane < 8) ? 16 * lane
                 : (lane < 16 ? 16 * (lane - 8) + 8 : 0);

    const float Dh = D[h];
    float (*bw)[10] = buf[wid];

    #pragma unroll 1
    for (int nt = 0; nt < 8; nt++) {
        const int n0 = wid * 64 + nt * 8;
        float cc[4] = {0.f, 0.f, 0.f, 0.f};

        #pragma unroll
        for (int s = 0; s < 9; s++) {
            const int base = 128 + 16 * (n0 - s);
            uint32_t bb[2];
            LDMATRIX_X2(bb[0], bb[1], uh_u32 + (uint32_t)(base + lm) * 2u);
            mma_f16(cc, af[s], bb);
        }

        bw[r][2 * c]         = cc[0];
        bw[r][2 * c + 1]     = cc[1];
        bw[r + 8][2 * c]     = cc[2];
        bw[r + 8][2 * c + 1] = cc[3];
        __syncwarp();

        const int lbase = 16 * n0 + 4 * lane;
        float4 uv = *(const float4*)&urow[lbase];
        const float us4[4] = {uv.x, uv.y, uv.z, uv.w};
        __half hv[4];
        #pragma unroll
        for (int j = 0; j < 4; j++) {
            int li = 4 * lane + j;
            float x = bw[li & 15][li >> 4] + Dh * us4[j];
            float gv = 0.5f * x * (1.f + erff(x * 0.70710678118654752f));
            hv[j] = __float2half_rn(gv);
        }
        *(uint2*)&yrow[lbase] = *(const uint2*)hv;
        __syncwarp();
    }
}

// ============================================================================
// Kernel 2: fp16 mma m16n8k16 GEMM + fused GLU — R12 structure, but the
// mainloop uses fp16-ACCUM mma (C=0 per mma, promoted to fp32 in CUDA cores).
// CTA: 128(h) x 128(l), both gates. 512 threads (4 warps/SMSP).
// BK=32, 4-stage cp.async pipeline, one barrier per chunk.
// ============================================================================
#define BK       32
#define NKC      (H_ / BK)          // 64
#define BN       128
#define A_STRH   40
#define B_STRH   136
#define OFF_AA   0
#define OFF_AG   (128 * A_STRH)
#define OFF_B    (2 * 128 * A_STRH)
#define STAGE_H  (2 * 128 * A_STRH + BK * B_STRH)
#define NSTG     4
#define SMEM_BYTES (NSTG * STAGE_H * 2)

__global__ __launch_bounds__(512, 1) void gemm_glu_tc(
    const float* __restrict__ bias,
    float* __restrict__ out)
{
    extern __shared__ __half smem_h[];
    const uint32_t smem_u = smem_to_u32(smem_h);

    const int tid  = threadIdx.x;
    const int wid  = tid >> 5;
    const int lane = tid & 31;
    const int l0   = blockIdx.x * BN;
    const int h0   = blockIdx.y * 128;
    const int b    = blockIdx.z;

    const __half* Y = g_y + (size_t)b * H_ * L_;
    const __half* W = g_wh;

    const int a_row = tid >> 2;
    const int a_q   = (tid & 3) * 8;
    const int b_row = tid >> 4;
    const int b_col = (tid & 15) * 8;

    auto issue = [&](int k0, int s) {
        uint32_t sb = smem_u + (uint32_t)(s * STAGE_H) * 2u;
        cp16(sb + (uint32_t)(OFF_AA + a_row * A_STRH + a_q) * 2u,
             &W[(size_t)(h0 + a_row) * H_ + k0 + a_q]);
        cp16(sb + (uint32_t)(OFF_AG + a_row * A_STRH + a_q) * 2u,
             &W[(size_t)(h0 + a_row + H_) * H_ + k0 + a_q]);
        cp16(sb + (uint32_t)(OFF_B + b_row * B_STRH + b_col) * 2u,
             &Y[(size_t)(k0 + b_row) * L_ + l0 + b_col]);
    };

    float acc_a[2][4][4];
    float acc_g[2][4][4];
    #pragma unroll
    for (int mt = 0; mt < 2; mt++)
        #pragma unroll
        for (int nt = 0; nt < 4; nt++)
            #pragma unroll
            for (int q = 0; q < 4; q++) { acc_a[mt][nt][q] = 0.f; acc_g[mt][nt][q] = 0.f; }

    const int wm  = (wid & 3) * 32;
    const int wn  = (wid >> 2) * 32;
    const int g   = lane >> 2;
    const int t   = lane & 3;

    const int lm_k = (lane & 7) | (((lane >> 3) & 1) << 3);
    const int lm_n = (lane >> 4) << 3;
    const uint32_t b_lane_off =
        (uint32_t)(OFF_B + lm_k * B_STRH + wn + lm_n) * 2u;

    const uint32_t a_lane_base =
        (uint32_t)((wm + (lane & 15)) * A_STRH + ((lane >> 4) << 3)) * 2u;

    issue(0,      0);  CP_COMMIT();
    issue(BK,     1);  CP_COMMIT();
    issue(2 * BK, 2);  CP_COMMIT();

    for (int kc = 0; kc < NKC; kc++) {
        if (kc <= NKC - 3)      { CP_WAIT(2); }
        else if (kc == NKC - 2) { CP_WAIT(1); }
        else                    { CP_WAIT(0); }
        __syncthreads();

        if (kc + 3 < NKC) {
            issue((kc + 3) * BK, (kc + 3) & 3);
            CP_COMMIT();
        }

        const uint32_t stg_u = smem_u + (uint32_t)((kc & 3) * STAGE_H) * 2u;
        const uint32_t a_base = stg_u + (uint32_t)(OFF_AA * 2) + a_lane_base;
        const uint32_t g_base = stg_u + (uint32_t)(OFF_AG * 2) + a_lane_base;

        #pragma unroll
        for (int ks = 0; ks < 2; ks++) {
            const int kb = ks * 16;

            uint32_t bb[4][2];
            LDMATRIX_X4_TRANS(bb[0][0], bb[0][1], bb[1][0], bb[1][1],
                              stg_u + b_lane_off + (uint32_t)(kb * B_STRH) * 2u);
            LDMATRIX_X4_TRANS(bb[2][0], bb[2][1], bb[3][0], bb[3][1],
                              stg_u + b_lane_off + (uint32_t)(kb * B_STRH + 16) * 2u);

            #pragma unroll
            for (int mt = 0; mt < 2; mt++) {
                const uint32_t moff = (uint32_t)(mt * 16 * A_STRH + kb) * 2u;
                uint32_t af[4], gf[4];
                LDMATRIX_X4(af[0], af[1], af[2], af[3], a_base + moff);
                LDMATRIX_X4(gf[0], gf[1], gf[2], gf[3], g_base + moff);
                #pragma unroll
                for (int nt = 0; nt < 4; nt++) {
                    mma_f16h_acc(acc_a[mt][nt], af, bb[nt]);
                    mma_f16h_acc(acc_g[mt][nt], gf, bb[nt]);
                }
            }
        }
    }

    // ---- epilogue: bias + GLU (fast-math), float2 stores ----
    #pragma unroll
    for (int mt = 0; mt < 2; mt++) {
        const int h_lo = h0 + wm + mt * 16 + g;
        const int h_hi = h_lo + 8;
        const float ba0 = bias[h_lo],  bg0 = bias[h_lo + H_];
        const float ba1 = bias[h_hi],  bg1 = bias[h_hi + H_];
        #pragma unroll
        for (int nt = 0; nt < 4; nt++) {
            const int l = l0 + wn + nt * 8 + t * 2;
            float za, zg;
            float2 o2;

            za = acc_a[mt][nt][0] + ba0; zg = acc_g[mt][nt][0] + bg0;
            o2.x = __fdividef(za, 1.f + __expf(-zg));
            za = acc_a[mt][nt][1] + ba0; zg = acc_g[mt][nt][1] + bg0;
            o2.y = __fdividef(za, 1.f + __expf(-zg));
            *(float2*)&out[((size_t)b * H_ + h_lo) * L_ + l] = o2;

            za = acc_a[mt][nt][2] + ba1; zg = acc_g[mt][nt][2] + bg1;
            o2.x = __fdividef(za, 1.f + __expf(-zg));
            za = acc_a[mt][nt][3] + ba1; zg = acc_g[mt][nt][3] + bg1;
            o2.y = __fdividef(za, 1.f + __expf(-zg));
            *(float2*)&out[((size_t)b * H_ + h_hi) * L_ + l] = o2;
        }
    }
}

// ============================================================================
extern "C" void kernel_launch(void* const* d_in, const int* in_sizes, int n_in,
                              void* d_out, int out_size)
{
    const float* u    = (const float*)d_in[0];   // [B,H,L]
    const float* kern = (const float*)d_in[1];   // [1,H,128]
    const float* D    = (const float*)d_in[2];   // [1,H]
    const float* W    = (const float*)d_in[3];   // [2H,H]
    const float* bias = (const float*)d_in[4];   // [2H]
    float* out = (float*)d_out;                  // [B,H,L]

    conv_gelu_mma<<<NCONV + NWCVT, 128>>>(u, kern, D, W);

    cudaFuncSetAttribute(gemm_glu_tc,
                         cudaFuncAttributeMaxDynamicSharedMemorySize, SMEM_BYTES);
    dim3 grid(L_ / BN, H_ / 128, B_);
    gemm_glu_tc<<<grid, 512, SMEM_BYTES>>>(bias, out);
}

// round 15
// speedup vs baseline: 1.3669x; 1.3669x over previous
#include <cuda_runtime.h>
#include <cuda_fp16.h>
#include <cstdint>
#include <math.h>

#define B_  2
#define H_  2048
#define L_  4096
#define LK  128
#define LAM 0.003f

// Scratch: gelu(conv(u)+D*u) as fp16, layout [B, H, L]
__device__ __half g_y[(size_t)B_ * H_ * L_];
// fp16 copy of W [2H, H]
__device__ __half g_wh[(size_t)2 * H_ * H_];

// ============================================================================
// Helpers
// ============================================================================
__device__ __forceinline__ uint32_t smem_to_u32(const void* p) {
    uint32_t a;
    asm("{ .reg .u64 t; cvta.to.shared.u64 t, %1; cvt.u32.u64 %0, t; }"
        : "=r"(a) : "l"(p));
    return a;
}
__device__ __forceinline__ void cp16(uint32_t dst, const void* src) {
    asm volatile("cp.async.cg.shared.global [%0], [%1], 16;"
                 :: "r"(dst), "l"(src));
}
#define CP_COMMIT() asm volatile("cp.async.commit_group;" ::: "memory")
#define CP_WAIT(N)  asm volatile("cp.async.wait_group %0;" :: "n"(N) : "memory")

#define LDMATRIX_X2(r0, r1, addr) \
    asm volatile("ldmatrix.sync.aligned.m8n8.x2.shared.b16 {%0,%1}, [%2];" \
                 : "=r"(r0), "=r"(r1) : "r"(addr))

#define LDMATRIX_X4(r0, r1, r2, r3, addr) \
    asm volatile("ldmatrix.sync.aligned.m8n8.x4.shared.b16 {%0,%1,%2,%3}, [%4];" \
                 : "=r"(r0), "=r"(r1), "=r"(r2), "=r"(r3) : "r"(addr))

#define LDMATRIX_X4_TRANS(r0, r1, r2, r3, addr) \
    asm volatile("ldmatrix.sync.aligned.m8n8.x4.trans.shared.b16 {%0,%1,%2,%3}, [%4];" \
                 : "=r"(r0), "=r"(r1), "=r"(r2), "=r"(r3) : "r"(addr))

__device__ __forceinline__ void mma_f16(float* c, const uint32_t* a, const uint32_t* b) {
    asm volatile(
        "mma.sync.aligned.m16n8k16.row.col.f32.f16.f16.f32 "
        "{%0,%1,%2,%3}, {%4,%5,%6,%7}, {%8,%9}, {%0,%1,%2,%3};"
        : "+f"(c[0]), "+f"(c[1]), "+f"(c[2]), "+f"(c[3])
        : "r"(a[0]), "r"(a[1]), "r"(a[2]), "r"(a[3]), "r"(b[0]), "r"(b[1]));
}

// ============================================================================
// Kernel 1: fused. Blocks [0,4096): Toeplitz tensor-core FIR conv + fp32 D
// skip + exact GELU -> fp16. Blocks [4096,6144): W -> fp16 conversion.
// ============================================================================
#define NCONV (B_ * H_)
#define NWCVT 2048

__global__ __launch_bounds__(128) void conv_gelu_mma(
    const float* __restrict__ u,
    const float* __restrict__ kern,
    const float* __restrict__ D,
    const float* __restrict__ W)
{
    const int tid = threadIdx.x;

    if (blockIdx.x >= NCONV) {
        size_t base = ((size_t)(blockIdx.x - NCONV) * 4096) + (size_t)tid * 8;
        #pragma unroll
        for (int it = 0; it < 4; it++) {
            size_t i = base + (size_t)it * 1024;
            float4 v0 = *(const float4*)(W + i);
            float4 v1 = *(const float4*)(W + i + 4);
            __half2 hh[4];
            hh[0] = __floats2half2_rn(v0.x, v0.y);
            hh[1] = __floats2half2_rn(v0.z, v0.w);
            hh[2] = __floats2half2_rn(v1.x, v1.y);
            hh[3] = __floats2half2_rn(v1.z, v1.w);
            *(uint4*)(g_wh + i) = *(const uint4*)hh;
        }
        return;
    }

    __shared__ __half uh[4224];
    __shared__ __half At[9][16][24];
    __shared__ float  ks[LK];
    __shared__ float  buf[4][16][10];

    const int bh   = blockIdx.x;
    const int b    = bh / H_;
    const int h    = bh % H_;
    const int wid  = tid >> 5;
    const int lane = tid & 31;

    const float* urow = u   + ((size_t)b * H_ + h) * L_;
    __half*      yrow = g_y + ((size_t)b * H_ + h) * L_;

    {
        float kv = kern[h * LK + tid];
        float a  = fabsf(kv) - LAM;
        a = a > 0.f ? a : 0.f;
        ks[tid] = (kv > 0.f) ? a : ((kv < 0.f) ? -a : 0.f);
    }
    for (int idx = tid; idx < 4224; idx += 128) {
        int l = idx - 128;
        uh[idx] = (l >= 0) ? __float2half_rn(urow[l]) : __float2half_rn(0.f);
    }
    __syncthreads();
    for (int e = tid; e < 9 * 256; e += 128) {
        int s = e >> 8, rr = e & 255, i = rr >> 4, t = rr & 15;
        int d = i - t + 16 * s;
        At[s][i][t] = (d >= 0 && d < LK) ? __float2half_rn(ks[d])
                                         : __float2half_rn(0.f);
    }
    __syncthreads();

    const int r = lane >> 2;
    const int c = lane & 3;
    uint32_t af[9][4];
    #pragma unroll
    for (int s = 0; s < 9; s++) {
        af[s][0] = *(const uint32_t*)&At[s][r][2 * c];
        af[s][1] = *(const uint32_t*)&At[s][r + 8][2 * c];
        af[s][2] = *(const uint32_t*)&At[s][r][2 * c + 8];
        af[s][3] = *(const uint32_t*)&At[s][r + 8][2 * c + 8];
    }

    const uint32_t uh_u32 = smem_to_u32(uh);
    const int lm = (lane < 8) ? 16 * lane
                 : (lane < 16 ? 16 * (lane - 8) + 8 : 0);

    const float Dh = D[h];
    float (*bw)[10] = buf[wid];

    #pragma unroll 1
    for (int nt = 0; nt < 8; nt++) {
        const int n0 = wid * 64 + nt * 8;
        float cc[4] = {0.f, 0.f, 0.f, 0.f};

        #pragma unroll
        for (int s = 0; s < 9; s++) {
            const int base = 128 + 16 * (n0 - s);
            uint32_t bb[2];
            LDMATRIX_X2(bb[0], bb[1], uh_u32 + (uint32_t)(base + lm) * 2u);
            mma_f16(cc, af[s], bb);
        }

        bw[r][2 * c]         = cc[0];
        bw[r][2 * c + 1]     = cc[1];
        bw[r + 8][2 * c]     = cc[2];
        bw[r + 8][2 * c + 1] = cc[3];
        __syncwarp();

        const int lbase = 16 * n0 + 4 * lane;
        float4 uv = *(const float4*)&urow[lbase];
        const float us4[4] = {uv.x, uv.y, uv.z, uv.w};
        __half hv[4];
        #pragma unroll
        for (int j = 0; j < 4; j++) {
            int li = 4 * lane + j;
            float x = bw[li & 15][li >> 4] + Dh * us4[j];
            float gv = 0.5f * x * (1.f + erff(x * 0.70710678118654752f));
            hv[j] = __float2half_rn(gv);
        }
        *(uint2*)&yrow[lbase] = *(const uint2*)hv;
        __syncwarp();
    }
}

// ============================================================================
// Kernel 2: fp16 mma.sync m16n8k16 GEMM + fused GLU. R12 structure with
// fp32-accum mma, BK=64 (half the per-chunk barrier/wait overhead).
// CTA: 128(h) x 128(l), both gates. 512 threads (4 warps/SMSP).
// A/G frags: ldmatrix.x4 from [m][k] (stride 72 halves, conflict-free).
// B frags:   ldmatrix.x4.trans from [k][n] (stride 136 halves).
// 3-stage cp.async pipeline, one barrier per chunk.
// ============================================================================
#define BK       64
#define NKC      (H_ / BK)          // 32
#define BN       128
#define A_STRH   72                  // 64 k-halves + 8 pad
#define B_STRH   136
#define OFF_AA   0
#define OFF_AG   (128 * A_STRH)                      // 9216 halves
#define OFF_B    (2 * 128 * A_STRH)                  // 18432 halves
#define STAGE_H  (2 * 128 * A_STRH + BK * B_STRH)    // 27136 halves = 54272 B
#define NSTG     3
#define SMEM_BYTES (NSTG * STAGE_H * 2)              // 162816 B

__global__ __launch_bounds__(512, 1) void gemm_glu_tc(
    const float* __restrict__ bias,
    float* __restrict__ out)
{
    extern __shared__ __half smem_h[];
    const uint32_t smem_u = smem_to_u32(smem_h);

    const int tid  = threadIdx.x;
    const int wid  = tid >> 5;
    const int lane = tid & 31;
    const int l0   = blockIdx.x * BN;
    const int h0   = blockIdx.y * 128;
    const int b    = blockIdx.z;

    const __half* Y = g_y + (size_t)b * H_ * L_;
    const __half* W = g_wh;

    // cp.async coordinates
    const int a_row = tid >> 2;          // 0..127
    const int a_q   = (tid & 3) * 16;    // k offset 0,16,32,48 halves
    const int b_row = tid >> 4;          // 0..31 (2 iters of +32)
    const int b_col = (tid & 15) * 8;    // n offset 0..120 halves

    auto issue = [&](int k0, int s) {
        uint32_t sb = smem_u + (uint32_t)(s * STAGE_H) * 2u;
        cp16(sb + (uint32_t)(OFF_AA + a_row * A_STRH + a_q) * 2u,
             &W[(size_t)(h0 + a_row) * H_ + k0 + a_q]);
        cp16(sb + (uint32_t)(OFF_AA + a_row * A_STRH + a_q + 8) * 2u,
             &W[(size_t)(h0 + a_row) * H_ + k0 + a_q + 8]);
        cp16(sb + (uint32_t)(OFF_AG + a_row * A_STRH + a_q) * 2u,
             &W[(size_t)(h0 + a_row + H_) * H_ + k0 + a_q]);
        cp16(sb + (uint32_t)(OFF_AG + a_row * A_STRH + a_q + 8) * 2u,
             &W[(size_t)(h0 + a_row + H_) * H_ + k0 + a_q + 8]);
        cp16(sb + (uint32_t)(OFF_B + b_row * B_STRH + b_col) * 2u,
             &Y[(size_t)(k0 + b_row) * L_ + l0 + b_col]);
        cp16(sb + (uint32_t)(OFF_B + (b_row + 32) * B_STRH + b_col) * 2u,
             &Y[(size_t)(k0 + b_row + 32) * L_ + l0 + b_col]);
    };

    float acc_a[2][4][4];
    float acc_g[2][4][4];
    #pragma unroll
    for (int mt = 0; mt < 2; mt++)
        #pragma unroll
        for (int nt = 0; nt < 4; nt++)
            #pragma unroll
            for (int q = 0; q < 4; q++) { acc_a[mt][nt][q] = 0.f; acc_g[mt][nt][q] = 0.f; }

    const int wm  = (wid & 3) * 32;
    const int wn  = (wid >> 2) * 32;
    const int g   = lane >> 2;
    const int t   = lane & 3;

    const int lm_k = (lane & 7) | (((lane >> 3) & 1) << 3);
    const int lm_n = (lane >> 4) << 3;
    const uint32_t b_lane_off =
        (uint32_t)(OFF_B + lm_k * B_STRH + wn + lm_n) * 2u;

    const uint32_t a_lane_base =
        (uint32_t)((wm + (lane & 15)) * A_STRH + ((lane >> 4) << 3)) * 2u;

    // prefill 2 stages
    issue(0,  0);  CP_COMMIT();
    issue(BK, 1);  CP_COMMIT();

    for (int kc = 0; kc < NKC; kc++) {
        if (kc < NKC - 1) { CP_WAIT(1); } else { CP_WAIT(0); }
        __syncthreads();   // stage kc ready; stage kc-1 consumed by all

        if (kc + 2 < NKC) {
            issue((kc + 2) * BK, (kc + 2) % NSTG);   // overwrites stage (kc-1)%3
            CP_COMMIT();
        }

        const uint32_t stg_u = smem_u + (uint32_t)((kc % NSTG) * STAGE_H) * 2u;
        const uint32_t a_base = stg_u + a_lane_base;
        const uint32_t g_base = stg_u + (uint32_t)(OFF_AG * 2) + a_lane_base;

        #pragma unroll
        for (int ks = 0; ks < 4; ks++) {
            const int kb = ks * 16;

            uint32_t bb[4][2];
            LDMATRIX_X4_TRANS(bb[0][0], bb[0][1], bb[1][0], bb[1][1],
                              stg_u + b_lane_off + (uint32_t)(kb * B_STRH) * 2u);
            LDMATRIX_X4_TRANS(bb[2][0], bb[2][1], bb[3][0], bb[3][1],
                              stg_u + b_lane_off + (uint32_t)(kb * B_STRH + 16) * 2u);

            #pragma unroll
            for (int mt = 0; mt < 2; mt++) {
                const uint32_t moff = (uint32_t)(mt * 16 * A_STRH + kb) * 2u;
                uint32_t af[4], gf[4];
                LDMATRIX_X4(af[0], af[1], af[2], af[3], a_base + moff);
                LDMATRIX_X4(gf[0], gf[1], gf[2], gf[3], g_base + moff);
                #pragma unroll
                for (int nt = 0; nt < 4; nt++) {
                    mma_f16(acc_a[mt][nt], af, bb[nt]);
                    mma_f16(acc_g[mt][nt], gf, bb[nt]);
                }
            }
        }
    }

    // ---- epilogue: bias + GLU (fast-math), float2 stores ----
    #pragma unroll
    for (int mt = 0; mt < 2; mt++) {
        const int h_lo = h0 + wm + mt * 16 + g;
        const int h_hi = h_lo + 8;
        const float ba0 = bias[h_lo],  bg0 = bias[h_lo + H_];
        const float ba1 = bias[h_hi],  bg1 = bias[h_hi + H_];
        #pragma unroll
        for (int nt = 0; nt < 4; nt++) {
            const int l = l0 + wn + nt * 8 + t * 2;
            float za, zg;
            float2 o2;

            za = acc_a[mt][nt][0] + ba0; zg = acc_g[mt][nt][0] + bg0;
            o2.x = __fdividef(za, 1.f + __expf(-zg));
            za = acc_a[mt][nt][1] + ba0; zg = acc_g[mt][nt][1] + bg0;
            o2.y = __fdividef(za, 1.f + __expf(-zg));
            *(float2*)&out[((size_t)b * H_ + h_lo) * L_ + l] = o2;

            za = acc_a[mt][nt][2] + ba1; zg = acc_g[mt][nt][2] + bg1;
            o2.x = __fdividef(za, 1.f + __expf(-zg));
            za = acc_a[mt][nt][3] + ba1; zg = acc_g[mt][nt][3] + bg1;
            o2.y = __fdividef(za, 1.f + __expf(-zg));
            *(float2*)&out[((size_t)b * H_ + h_hi) * L_ + l] = o2;
        }
    }
}

// ============================================================================
extern "C" void kernel_launch(void* const* d_in, const int* in_sizes, int n_in,
                              void* d_out, int out_size)
{
    const float* u    = (const float*)d_in[0];   // [B,H,L]
    const float* kern = (const float*)d_in[1];   // [1,H,128]
    const float* D    = (const float*)d_in[2];   // [1,H]
    const float* W    = (const float*)d_in[3];   // [2H,H]
    const float* bias = (const float*)d_in[4];   // [2H]
    float* out = (float*)d_out;                  // [B,H,L]

    conv_gelu_mma<<<NCONV + NWCVT, 128>>>(u, kern, D, W);

    cudaFuncSetAttribute(gemm_glu_tc,
                         cudaFuncAttributeMaxDynamicSharedMemorySize, SMEM_BYTES);
    dim3 grid(L_ / BN, H_ / 128, B_);
    gemm_glu_tc<<<grid, 512, SMEM_BYTES>>>(bias, out);
}

// round 16
// speedup vs baseline: 1.3778x; 1.0080x over previous
#include <cuda_runtime.h>
#include <cuda_fp16.h>
#include <cstdint>
#include <math.h>

#define B_  2
#define H_  2048
#define L_  4096
#define LK  128
#define LAM 0.003f

// Scratch: gelu(conv(u)+D*u) as fp16, layout [B, H, L]
__device__ __half g_y[(size_t)B_ * H_ * L_];
// fp16 copy of W [2H, H]
__device__ __half g_wh[(size_t)2 * H_ * H_];

// ============================================================================
// Helpers
// ============================================================================
__device__ __forceinline__ uint32_t smem_to_u32(const void* p) {
    uint32_t a;
    asm("{ .reg .u64 t; cvta.to.shared.u64 t, %1; cvt.u32.u64 %0, t; }"
        : "=r"(a) : "l"(p));
    return a;
}
__device__ __forceinline__ void cp16(uint32_t dst, const void* src) {
    asm volatile("cp.async.cg.shared.global [%0], [%1], 16;"
                 :: "r"(dst), "l"(src));
}
#define CP_COMMIT() asm volatile("cp.async.commit_group;" ::: "memory")
#define CP_WAIT(N)  asm volatile("cp.async.wait_group %0;" :: "n"(N) : "memory")

#define LDMATRIX_X2(r0, r1, addr) \
    asm volatile("ldmatrix.sync.aligned.m8n8.x2.shared.b16 {%0,%1}, [%2];" \
                 : "=r"(r0), "=r"(r1) : "r"(addr))

#define LDMATRIX_X4(r0, r1, r2, r3, addr) \
    asm volatile("ldmatrix.sync.aligned.m8n8.x4.shared.b16 {%0,%1,%2,%3}, [%4];" \
                 : "=r"(r0), "=r"(r1), "=r"(r2), "=r"(r3) : "r"(addr))

#define LDMATRIX_X4_TRANS(r0, r1, r2, r3, addr) \
    asm volatile("ldmatrix.sync.aligned.m8n8.x4.trans.shared.b16 {%0,%1,%2,%3}, [%4];" \
                 : "=r"(r0), "=r"(r1), "=r"(r2), "=r"(r3) : "r"(addr))

__device__ __forceinline__ void mma_f16(float* c, const uint32_t* a, const uint32_t* b) {
    asm volatile(
        "mma.sync.aligned.m16n8k16.row.col.f32.f16.f16.f32 "
        "{%0,%1,%2,%3}, {%4,%5,%6,%7}, {%8,%9}, {%0,%1,%2,%3};"
        : "+f"(c[0]), "+f"(c[1]), "+f"(c[2]), "+f"(c[3])
        : "r"(a[0]), "r"(a[1]), "r"(a[2]), "r"(a[3]), "r"(b[0]), "r"(b[1]));
}

// ============================================================================
// Kernel 1: fused. Blocks [0,4096): Toeplitz tensor-core FIR conv + D skip
// (u from smem, fp16) + exact GELU -> fp16. Blocks [4096,6144): W -> fp16.
// ============================================================================
#define NCONV (B_ * H_)
#define NWCVT 2048

__global__ __launch_bounds__(128) void conv_gelu_mma(
    const float* __restrict__ u,
    const float* __restrict__ kern,
    const float* __restrict__ D,
    const float* __restrict__ W)
{
    const int tid = threadIdx.x;

    if (blockIdx.x >= NCONV) {
        size_t base = ((size_t)(blockIdx.x - NCONV) * 4096) + (size_t)tid * 8;
        #pragma unroll
        for (int it = 0; it < 4; it++) {
            size_t i = base + (size_t)it * 1024;
            float4 v0 = *(const float4*)(W + i);
            float4 v1 = *(const float4*)(W + i + 4);
            __half2 hh[4];
            hh[0] = __floats2half2_rn(v0.x, v0.y);
            hh[1] = __floats2half2_rn(v0.z, v0.w);
            hh[2] = __floats2half2_rn(v1.x, v1.y);
            hh[3] = __floats2half2_rn(v1.z, v1.w);
            *(uint4*)(g_wh + i) = *(const uint4*)hh;
        }
        return;
    }

    __shared__ __half uh[4224];
    __shared__ __half At[9][16][24];
    __shared__ float  ks[LK];
    __shared__ float  buf[4][16][10];

    const int bh   = blockIdx.x;
    const int b    = bh / H_;
    const int h    = bh % H_;
    const int wid  = tid >> 5;
    const int lane = tid & 31;

    const float* urow = u   + ((size_t)b * H_ + h) * L_;
    __half*      yrow = g_y + ((size_t)b * H_ + h) * L_;

    {
        float kv = kern[h * LK + tid];
        float a  = fabsf(kv) - LAM;
        a = a > 0.f ? a : 0.f;
        ks[tid] = (kv > 0.f) ? a : ((kv < 0.f) ? -a : 0.f);
    }
    for (int idx = tid; idx < 4224; idx += 128) {
        int l = idx - 128;
        uh[idx] = (l >= 0) ? __float2half_rn(urow[l]) : __float2half_rn(0.f);
    }
    __syncthreads();
    for (int e = tid; e < 9 * 256; e += 128) {
        int s = e >> 8, rr = e & 255, i = rr >> 4, t = rr & 15;
        int d = i - t + 16 * s;
        At[s][i][t] = (d >= 0 && d < LK) ? __float2half_rn(ks[d])
                                         : __float2half_rn(0.f);
    }
    __syncthreads();

    const int r = lane >> 2;
    const int c = lane & 3;
    uint32_t af[9][4];
    #pragma unroll
    for (int s = 0; s < 9; s++) {
        af[s][0] = *(const uint32_t*)&At[s][r][2 * c];
        af[s][1] = *(const uint32_t*)&At[s][r + 8][2 * c];
        af[s][2] = *(const uint32_t*)&At[s][r][2 * c + 8];
        af[s][3] = *(const uint32_t*)&At[s][r + 8][2 * c + 8];
    }

    const uint32_t uh_u32 = smem_to_u32(uh);
    const int lm = (lane < 8) ? 16 * lane
                 : (lane < 16 ? 16 * (lane - 8) + 8 : 0);

    const float Dh = D[h];
    float (*bw)[10] = buf[wid];

    #pragma unroll 1
    for (int nt = 0; nt < 8; nt++) {
        const int n0 = wid * 64 + nt * 8;
        float cc[4] = {0.f, 0.f, 0.f, 0.f};

        #pragma unroll
        for (int s = 0; s < 9; s++) {
            const int base = 128 + 16 * (n0 - s);
            uint32_t bb[2];
            LDMATRIX_X2(bb[0], bb[1], uh_u32 + (uint32_t)(base + lm) * 2u);
            mma_f16(cc, af[s], bb);
        }

        bw[r][2 * c]         = cc[0];
        bw[r][2 * c + 1]     = cc[1];
        bw[r + 8][2 * c]     = cc[2];
        bw[r + 8][2 * c + 1] = cc[3];
        __syncwarp();

        // epilogue: u skip read from smem (fp16), no global reload
        const int lbase = 16 * n0 + 4 * lane;
        uint2 up = *(const uint2*)&uh[128 + lbase];
        const __half2* uh2 = (const __half2*)&up;
        float2 u01 = __half22float2(uh2[0]);
        float2 u23 = __half22float2(uh2[1]);
        const float us4[4] = {u01.x, u01.y, u23.x, u23.y};
        __half hv[4];
        #pragma unroll
        for (int j = 0; j < 4; j++) {
            int li = 4 * lane + j;
            float x = bw[li & 15][li >> 4] + Dh * us4[j];
            float gv = 0.5f * x * (1.f + erff(x * 0.70710678118654752f));
            hv[j] = __float2half_rn(gv);
        }
        *(uint2*)&yrow[lbase] = *(const uint2*)hv;
        __syncwarp();
    }
}

// ============================================================================
// Kernel 2: fp16 mma.sync m16n8k16 GEMM + fused GLU. BK=64, fp32-accum mma.
// CTA: 128(h) x 128(l), both gates. 512 threads (4 warps/SMSP).
// A/G frags: ldmatrix.x4 from [m][k] (stride 72 halves, conflict-free).
// B frags:   ldmatrix.x4.trans from [k][n] (stride 136 halves).
// 3-stage cp.async pipeline, one barrier per chunk.  (R15 best config.)
// ============================================================================
#define BK       64
#define NKC      (H_ / BK)          // 32
#define BN       128
#define A_STRH   72                  // 64 k-halves + 8 pad
#define B_STRH   136
#define OFF_AA   0
#define OFF_AG   (128 * A_STRH)                      // 9216 halves
#define OFF_B    (2 * 128 * A_STRH)                  // 18432 halves
#define STAGE_H  (2 * 128 * A_STRH + BK * B_STRH)    // 27136 halves = 54272 B
#define NSTG     3
#define SMEM_BYTES (NSTG * STAGE_H * 2)              // 162816 B

__global__ __launch_bounds__(512, 1) void gemm_glu_tc(
    const float* __restrict__ bias,
    float* __restrict__ out)
{
    extern __shared__ __half smem_h[];
    const uint32_t smem_u = smem_to_u32(smem_h);

    const int tid  = threadIdx.x;
    const int wid  = tid >> 5;
    const int lane = tid & 31;
    const int l0   = blockIdx.x * BN;
    const int h0   = blockIdx.y * 128;
    const int b    = blockIdx.z;

    const __half* Y = g_y + (size_t)b * H_ * L_;
    const __half* W = g_wh;

    const int a_row = tid >> 2;          // 0..127
    const int a_q   = (tid & 3) * 16;    // k offset 0,16,32,48 halves
    const int b_row = tid >> 4;          // 0..31 (2 iters of +32)
    const int b_col = (tid & 15) * 8;    // n offset 0..120 halves

    auto issue = [&](int k0, int s) {
        uint32_t sb = smem_u + (uint32_t)(s * STAGE_H) * 2u;
        cp16(sb + (uint32_t)(OFF_AA + a_row * A_STRH + a_q) * 2u,
             &W[(size_t)(h0 + a_row) * H_ + k0 + a_q]);
        cp16(sb + (uint32_t)(OFF_AA + a_row * A_STRH + a_q + 8) * 2u,
             &W[(size_t)(h0 + a_row) * H_ + k0 + a_q + 8]);
        cp16(sb + (uint32_t)(OFF_AG + a_row * A_STRH + a_q) * 2u,
             &W[(size_t)(h0 + a_row + H_) * H_ + k0 + a_q]);
        cp16(sb + (uint32_t)(OFF_AG + a_row * A_STRH + a_q + 8) * 2u,
             &W[(size_t)(h0 + a_row + H_) * H_ + k0 + a_q + 8]);
        cp16(sb + (uint32_t)(OFF_B + b_row * B_STRH + b_col) * 2u,
             &Y[(size_t)(k0 + b_row) * L_ + l0 + b_col]);
        cp16(sb + (uint32_t)(OFF_B + (b_row + 32) * B_STRH + b_col) * 2u,
             &Y[(size_t)(k0 + b_row + 32) * L_ + l0 + b_col]);
    };

    float acc_a[2][4][4];
    float acc_g[2][4][4];
    #pragma unroll
    for (int mt = 0; mt < 2; mt++)
        #pragma unroll
        for (int nt = 0; nt < 4; nt++)
            #pragma unroll
            for (int q = 0; q < 4; q++) { acc_a[mt][nt][q] = 0.f; acc_g[mt][nt][q] = 0.f; }

    const int wm  = (wid & 3) * 32;
    const int wn  = (wid >> 2) * 32;
    const int g   = lane >> 2;
    const int t   = lane & 3;

    const int lm_k = (lane & 7) | (((lane >> 3) & 1) << 3);
    const int lm_n = (lane >> 4) << 3;
    const uint32_t b_lane_off =
        (uint32_t)(OFF_B + lm_k * B_STRH + wn + lm_n) * 2u;

    const uint32_t a_lane_base =
        (uint32_t)((wm + (lane & 15)) * A_STRH + ((lane >> 4) << 3)) * 2u;

    issue(0,  0);  CP_COMMIT();
    issue(BK, 1);  CP_COMMIT();

    for (int kc = 0; kc < NKC; kc++) {
        if (kc < NKC - 1) { CP_WAIT(1); } else { CP_WAIT(0); }
        __syncthreads();   // stage kc ready; stage kc-1 consumed by all

        if (kc + 2 < NKC) {
            issue((kc + 2) * BK, (kc + 2) % NSTG);   // overwrites stage (kc-1)%3
            CP_COMMIT();
        }

        const uint32_t stg_u = smem_u + (uint32_t)((kc % NSTG) * STAGE_H) * 2u;
        const uint32_t a_base = stg_u + a_lane_base;
        const uint32_t g_base = stg_u + (uint32_t)(OFF_AG * 2) + a_lane_base;

        #pragma unroll
        for (int ks = 0; ks < 4; ks++) {
            const int kb = ks * 16;

            uint32_t bb[4][2];
            LDMATRIX_X4_TRANS(bb[0][0], bb[0][1], bb[1][0], bb[1][1],
                              stg_u + b_lane_off + (uint32_t)(kb * B_STRH) * 2u);
            LDMATRIX_X4_TRANS(bb[2][0], bb[2][1], bb[3][0], bb[3][1],
                              stg_u + b_lane_off + (uint32_t)(kb * B_STRH + 16) * 2u);

            #pragma unroll
            for (int mt = 0; mt < 2; mt++) {
                const uint32_t moff = (uint32_t)(mt * 16 * A_STRH + kb) * 2u;
                uint32_t af[4], gf[4];
                LDMATRIX_X4(af[0], af[1], af[2], af[3], a_base + moff);
                LDMATRIX_X4(gf[0], gf[1], gf[2], gf[3], g_base + moff);
                #pragma unroll
                for (int nt = 0; nt < 4; nt++) {
                    mma_f16(acc_a[mt][nt], af, bb[nt]);
                    mma_f16(acc_g[mt][nt], gf, bb[nt]);
                }
            }
        }
    }

    // ---- epilogue: bias + GLU (fast-math), float2 stores ----
    #pragma unroll
    for (int mt = 0; mt < 2; mt++) {
        const int h_lo = h0 + wm + mt * 16 + g;
        const int h_hi = h_lo + 8;
        const float ba0 = bias[h_lo],  bg0 = bias[h_lo + H_];
        const float ba1 = bias[h_hi],  bg1 = bias[h_hi + H_];
        #pragma unroll
        for (int nt = 0; nt < 4; nt++) {
            const int l = l0 + wn + nt * 8 + t * 2;
            float za, zg;
            float2 o2;

            za = acc_a[mt][nt][0] + ba0; zg = acc_g[mt][nt][0] + bg0;
            o2.x = __fdividef(za, 1.f + __expf(-zg));
            za = acc_a[mt][nt][1] + ba0; zg = acc_g[mt][nt][1] + bg0;
            o2.y = __fdividef(za, 1.f + __expf(-zg));
            *(float2*)&out[((size_t)b * H_ + h_lo) * L_ + l] = o2;

            za = acc_a[mt][nt][2] + ba1; zg = acc_g[mt][nt][2] + bg1;
            o2.x = __fdividef(za, 1.f + __expf(-zg));
            za = acc_a[mt][nt][3] + ba1; zg = acc_g[mt][nt][3] + bg1;
            o2.y = __fdividef(za, 1.f + __expf(-zg));
            *(float2*)&out[((size_t)b * H_ + h_hi) * L_ + l] = o2;
        }
    }
}

// ============================================================================
extern "C" void kernel_launch(void* const* d_in, const int* in_sizes, int n_in,
                              void* d_out, int out_size)
{
    const float* u    = (const float*)d_in[0];   // [B,H,L]
    const float* kern = (const float*)d_in[1];   // [1,H,128]
    const float* D    = (const float*)d_in[2];   // [1,H]
    const float* W    = (const float*)d_in[3];   // [2H,H]
    const float* bias = (const float*)d_in[4];   // [2H]
    float* out = (float*)d_out;                  // [B,H,L]

    conv_gelu_mma<<<NCONV + NWCVT, 128>>>(u, kern, D, W);

    cudaFuncSetAttribute(gemm_glu_tc,
                         cudaFuncAttributeMaxDynamicSharedMemorySize, SMEM_BYTES);
    dim3 grid(L_ / BN, H_ / 128, B_);
    gemm_glu_tc<<<grid, 512, SMEM_BYTES>>>(bias, out);
}